// round 13
// baseline (speedup 1.0000x reference)
#include <cuda_runtime.h>
#include <cstdint>

#define NODES   16384
#define NPG     128
#define NG      128
#define HID     128
#define KNN     24
#define SXT_S   132

typedef unsigned long long u64;

// ---------------- scratch ----------------
__device__ float g_feat_a[NODES * HID];
__device__ float g_feat_b[NODES * HID];
__device__ float g_pq[NODES * 2 * HID];
__device__ float g_wc3[3 * HID * 2 * HID];

__device__ __forceinline__ float elu_fast(float v) {
    return v > 0.0f ? v : (__expf(v) - 1.0f);
}

__device__ __forceinline__ unsigned fkey(float v) {
    unsigned b = __float_as_uint(v);
    return b ^ ((b & 0x80000000u) ? 0xffffffffu : 0x80000000u);
}

// ---- packed fp32x2 helpers (sm_103a FFMA2) ----
__device__ __forceinline__ u64 pack2(float lo, float hi) {
    u64 r; asm("mov.b64 %0,{%1,%2};" : "=l"(r) : "f"(lo), "f"(hi)); return r;
}
__device__ __forceinline__ void unpack2(u64 v, float& lo, float& hi) {
    asm("mov.b64 {%0,%1},%2;" : "=f"(lo), "=f"(hi) : "l"(v));
}
__device__ __forceinline__ void dfma(u64& d, u64 a, u64 b) {
    asm("fma.rn.f32x2 %0,%1,%2,%0;" : "+l"(d) : "l"(a), "l"(b));
}

// ---- cp.async helpers ----
__device__ __forceinline__ void cp16(void* smem, const void* gmem) {
    unsigned s = (unsigned)__cvta_generic_to_shared(smem);
    asm volatile("cp.async.cg.shared.global [%0], [%1], 16;\n" :: "r"(s), "l"(gmem));
}
__device__ __forceinline__ void cp_commit() { asm volatile("cp.async.commit_group;\n"); }
__device__ __forceinline__ void cp_wait0()  { asm volatile("cp.async.wait_group 0;\n"); }

// ---------------- pipelined 128x128-tile fp32 matmul (FFMA2, diag/anti) ----
// A staged as u64 pairs, natural AND swapped; B consumed as natural float2
// pairs. Inner loop: 32 FFMA2 + 6 LDS.128, ZERO MOVs.
// Per-element accumulation order over k is unchanged vs R5 (bit-identical).
// smem (u64 units): AsN [2][16*66], AsS [2][16*66]; then Bs float [2][2048].
#define MM_SMEM (2*16*66*8 * 2 + 2*16*128*4)

__global__ __launch_bounds__(256, 2) void mm_kernel(
    const float* __restrict__ A, const float* __restrict__ B,
    const float* __restrict__ bias, int biasLimit, int doElu,
    float* __restrict__ C, int N, int K)
{
    extern __shared__ u64 smu64[];
    u64*   AsN = smu64;                       // [2][16*66]
    u64*   AsS = smu64 + 2 * 16 * 66;         // [2][16*66]
    float* Bs  = (float*)(smu64 + 4 * 16 * 66);   // [2][16*128]

    const int tid = threadIdx.x;
    const int tx = tid & 15;
    const int ty = tid >> 4;
    const int rowBase = blockIdx.x * 128;
    const int colBase = blockIdx.y * 128;

    u64 accD[4][4], accA[4][4];
#pragma unroll
    for (int r = 0; r < 4; r++)
#pragma unroll
        for (int c = 0; c < 4; c++) { accD[r][c] = 0ull; accA[r][c] = 0ull; }

    // staging indices: 1024 (row-pair, k) slots, 4 per thread
    int mp[4], kx[4];
#pragma unroll
    for (int t = 0; t < 4; t++) {
        int idx = t * 256 + tid;
        mp[t] = idx >> 4;          // 0..63 row-pair
        kx[t] = idx & 15;          // k within tile
    }
    int bk[2], bn[2];
#pragma unroll
    for (int t = 0; t < 2; t++) {
        int idx = t * 256 + tid;
        bk[t] = idx >> 5;
        bn[t] = (idx & 31) * 4;
    }

    float aLo[4], aHi[4];
    // prologue: tile kk=0
#pragma unroll
    for (int t = 0; t < 4; t++) {
        const float* p = A + (size_t)(rowBase + 2 * mp[t]) * K + kx[t];
        aLo[t] = p[0];
        aHi[t] = p[K];
    }
#pragma unroll
    for (int t = 0; t < 2; t++)
        cp16(&Bs[bk[t] * 128 + bn[t]], &B[(size_t)bk[t] * N + colBase + bn[t]]);
    cp_commit();
#pragma unroll
    for (int t = 0; t < 4; t++) {
        AsN[kx[t] * 66 + mp[t]] = pack2(aLo[t], aHi[t]);
        AsS[kx[t] * 66 + mp[t]] = pack2(aHi[t], aLo[t]);
    }
    cp_wait0();
    __syncthreads();

    int buf = 0;
    for (int kk = 0; kk < K; kk += 16) {
        const int nkk = kk + 16;
        if (nkk < K) {
#pragma unroll
            for (int t = 0; t < 4; t++) {
                const float* p = A + (size_t)(rowBase + 2 * mp[t]) * K + nkk + kx[t];
                aLo[t] = p[0];
                aHi[t] = p[K];
            }
#pragma unroll
            for (int t = 0; t < 2; t++)
                cp16(&Bs[(buf ^ 1) * 2048 + bk[t] * 128 + bn[t]],
                     &B[(size_t)(nkk + bk[t]) * N + colBase + bn[t]]);
            cp_commit();
        }

        const u64*   AsNb = AsN + buf * (16 * 66);
        const u64*   AsSb = AsS + buf * (16 * 66);
        const float* Bsb  = Bs  + buf * 2048;
#pragma unroll
        for (int k = 0; k < 16; k++) {
            const u64* apN = AsNb + k * 66 + ty * 4;
            const u64* apS = AsSb + k * 66 + ty * 4;
            ulonglong2 n01 = *(const ulonglong2*)(apN);
            ulonglong2 n23 = *(const ulonglong2*)(apN + 2);
            ulonglong2 s01 = *(const ulonglong2*)(apS);
            ulonglong2 s23 = *(const ulonglong2*)(apS + 2);
            u64 aN[4] = {n01.x, n01.y, n23.x, n23.y};
            u64 aS[4] = {s01.x, s01.y, s23.x, s23.y};
            const u64* bp = (const u64*)(Bsb + k * 128 + tx * 8);
            ulonglong2 b01 = *(const ulonglong2*)(bp);
            ulonglong2 b23 = *(const ulonglong2*)(bp + 2);
            u64 b[4] = {b01.x, b01.y, b23.x, b23.y};
#pragma unroll
            for (int r = 0; r < 4; r++)
#pragma unroll
                for (int c = 0; c < 4; c++) {
                    dfma(accD[r][c], aN[r], b[c]);
                    dfma(accA[r][c], aS[r], b[c]);
                }
        }

        if (nkk < K) {
#pragma unroll
            for (int t = 0; t < 4; t++) {
                AsN[(buf ^ 1) * (16 * 66) + kx[t] * 66 + mp[t]] = pack2(aLo[t], aHi[t]);
                AsS[(buf ^ 1) * (16 * 66) + kx[t] * 66 + mp[t]] = pack2(aHi[t], aLo[t]);
            }
            cp_wait0();
            __syncthreads();
            buf ^= 1;
        }
    }

    // epilogue: reassemble 8x8 tile from diag/anti pairs
    float v[8][8];
#pragma unroll
    for (int r = 0; r < 4; r++)
#pragma unroll
        for (int c = 0; c < 4; c++) {
            float dlo, dhi, alo, ahi;
            unpack2(accD[r][c], dlo, dhi);
            unpack2(accA[r][c], alo, ahi);
            v[2 * r][2 * c]         = dlo;
            v[2 * r + 1][2 * c + 1] = dhi;
            v[2 * r + 1][2 * c]     = alo;
            v[2 * r][2 * c + 1]     = ahi;
        }
#pragma unroll
    for (int r = 0; r < 8; r++) {
        int row = rowBase + ty * 8 + r;
#pragma unroll
        for (int c = 0; c < 8; c++) {
            int col = colBase + tx * 8 + c;
            if (col < biasLimit) v[r][c] += bias[col];
            if (doElu) v[r][c] = elu_fast(v[r][c]);
        }
        float* p = C + (size_t)row * N + colBase + tx * 8;
        *(float4*)p       = make_float4(v[r][0], v[r][1], v[r][2], v[r][3]);
        *(float4*)(p + 4) = make_float4(v[r][4], v[r][5], v[r][6], v[r][7]);
    }
}

// ---------------- build [Wa-Wb | Wb] ---------------------------------------
__global__ void build_wcat(const float* __restrict__ w, float* __restrict__ wc)
{
    int idx = blockIdx.x * 256 + threadIdx.x;
    int d = idx >> 8;
    int n = idx & 255;
    float v;
    if (n < 128) v = w[d * 128 + n] - w[(128 + d) * 128 + n];
    else         v = w[(128 + d) * 128 + (n - 128)];
    wc[idx] = v;
}

// ---------------- per-HALF-graph kNN + select + aggregate (R10, verified) --
#define KNN_R0   16896
#define SMEM_KNN ((KNN_R0 + 128) * 4 + 64 * KNN * 4)

__global__ __launch_bounds__(512) void knn_agg(
    const float* __restrict__ X, const float* __restrict__ PQ,
    float* __restrict__ OUT)
{
    extern __shared__ float sm[];
    float* sXT = sm;
    float* sQ  = sm;
    float* sSq = sm + KNN_R0;
    int*   sList = (int*)(sSq + 128);

    const int g   = blockIdx.x >> 1;
    const int h   = blockIdx.x & 1;
    const int tid = threadIdx.x;
    const float* Xg  = X  + (size_t)g * NPG * HID;
    const float* PQg = PQ + (size_t)g * NPG * 2 * HID;

    for (int idx = tid; idx < NPG * HID; idx += 512) {
        int n = idx >> 7, f = idx & 127;
        sXT[f * SXT_S + n] = Xg[idx];
    }
    __syncthreads();

    if (tid < 128) {
        float s = 0.0f;
#pragma unroll 8
        for (int d = 0; d < 128; d++) {
            float v = sXT[d * SXT_S + tid];
            s += v * v;
        }
        sSq[tid] = s;
    }
    __syncthreads();

    const int w = tid >> 5;
    const int l = tid & 31;
    const int i0 = h * 64 + w * 4;
    const int j0 = l * 4;

    u64 acc2[2][4];
#pragma unroll
    for (int r = 0; r < 2; r++)
#pragma unroll
        for (int c = 0; c < 4; c++) acc2[r][c] = 0ull;

#pragma unroll 4
    for (int d = 0; d < 128; d++) {
        const float* rowp = sXT + d * SXT_S;
        ulonglong2 a01 = *(const ulonglong2*)(rowp + i0);
        u64 a[2] = {a01.x, a01.y};
        float4 bj = *(const float4*)(rowp + j0);
        u64 bd[4];
        bd[0] = pack2(bj.x, bj.x); bd[1] = pack2(bj.y, bj.y);
        bd[2] = pack2(bj.z, bj.z); bd[3] = pack2(bj.w, bj.w);
#pragma unroll
        for (int r = 0; r < 2; r++)
#pragma unroll
            for (int c = 0; c < 4; c++) dfma(acc2[r][c], a[r], bd[c]);
    }
    __syncthreads();

#pragma unroll
    for (int t = 0; t < 8; t++) {
        int idx = t * 512 + tid;
        int n = idx >> 5, c4 = (idx & 31) * 4;
        cp16(&sQ[n * 128 + c4], &PQg[n * 256 + 128 + c4]);
    }
    cp_commit();

    {
        float sqj[4];
#pragma unroll
        for (int c = 0; c < 4; c++) sqj[c] = sSq[j0 + c];
#pragma unroll
        for (int r = 0; r < 2; r++) {
            int ia = i0 + 2 * r;
            float sqa = sSq[ia], sqb = sSq[ia + 1];
#pragma unroll
            for (int c = 0; c < 4; c++) {
                float lo, hi;
                unpack2(acc2[r][c], lo, hi);
                unsigned kl = fkey(sqa + sqj[c] - 2.0f * lo);
                unsigned kh = fkey(sqb + sqj[c] - 2.0f * hi);
                acc2[r][c] = ((u64)kh << 32) | (u64)kl;
            }
        }
    }

    const unsigned lmask = (1u << l) - 1u;

#pragma unroll 1
    for (int r = 0; r < 2; r++) {
        unsigned ka[2][4];
#pragma unroll
        for (int c = 0; c < 4; c++) {
            ka[0][c] = (unsigned)acc2[r][c];
            ka[1][c] = (unsigned)(acc2[r][c] >> 32);
        }

        unsigned lo0 = 0, hi0 = 0xffffffffu, lo1 = 0, hi1 = 0xffffffffu;
#pragma unroll 1
        for (int it = 0; it < 32; it++) {
            unsigned m0 = lo0 + ((hi0 - lo0) >> 1);
            unsigned m1 = lo1 + ((hi1 - lo1) >> 1);
            int c0 = (ka[0][0] <= m0) + (ka[0][1] <= m0) + (ka[0][2] <= m0) + (ka[0][3] <= m0);
            int c1 = (ka[1][0] <= m1) + (ka[1][1] <= m1) + (ka[1][2] <= m1) + (ka[1][3] <= m1);
            c0 = __reduce_add_sync(0xffffffffu, c0);
            c1 = __reduce_add_sync(0xffffffffu, c1);
            if (c0 >= KNN) hi0 = m0; else lo0 = m0 + 1;
            if (c1 >= KNN) hi1 = m1; else lo1 = m1 + 1;
        }
        const unsigned KV[2] = {lo0, lo1};

#pragma unroll 1
        for (int rr = 0; rr < 2; rr++) {
            const int iloc = w * 4 + 2 * r + rr;
            const unsigned kv = KV[rr];

            int cl = 0;
#pragma unroll
            for (int c = 0; c < 4; c++) cl += (ka[rr][c] < kv) ? 1 : 0;
            int c0tot = __reduce_add_sync(0xffffffffu, cl);
            int rem = KNN - c0tot;

            bool eq[4], sel[4];
            unsigned bal[4];
#pragma unroll
            for (int c = 0; c < 4; c++) {
                eq[c] = (ka[rr][c] == kv);
                bal[c] = __ballot_sync(0xffffffffu, eq[c]);
            }
            int tiesLower = 0;
#pragma unroll
            for (int c = 0; c < 4; c++) tiesLower += __popc(bal[c] & lmask);
            int lp = 0;
#pragma unroll
            for (int c = 0; c < 4; c++) {
                sel[c] = (ka[rr][c] < kv) || (eq[c] && (tiesLower + lp) < rem);
                lp += eq[c] ? 1 : 0;
            }

            unsigned sbal[4];
#pragma unroll
            for (int c = 0; c < 4; c++) sbal[c] = __ballot_sync(0xffffffffu, sel[c]);
            int selLower = 0;
#pragma unroll
            for (int c = 0; c < 4; c++) selLower += __popc(sbal[c] & lmask);
            int sp = 0;
#pragma unroll
            for (int c = 0; c < 4; c++) {
                if (sel[c]) sList[iloc * KNN + selLower + sp] = j0 + c;
                sp += sel[c] ? 1 : 0;
            }
        }
    }

    cp_wait0();
    __syncthreads();

    const int fo = 4 * l;
#pragma unroll 1
    for (int rr = 0; rr < 4; rr++) {
        const int iloc = w * 4 + rr;
        const int i = h * 64 + iloc;
        float4 pv = *(const float4*)(PQg + (size_t)i * 256 + fo);
        float4 qm = make_float4(-3.0e38f, -3.0e38f, -3.0e38f, -3.0e38f);
#pragma unroll 4
        for (int it = 0; it < KNN; it++) {
            int j = sList[iloc * KNN + it];
            float4 qv = *(const float4*)(sQ + j * 128 + fo);
            qm.x = fmaxf(qm.x, qv.x);
            qm.y = fmaxf(qm.y, qv.y);
            qm.z = fmaxf(qm.z, qv.z);
            qm.w = fmaxf(qm.w, qv.w);
        }
        float4 ov;
        ov.x = elu_fast(pv.x + qm.x);
        ov.y = elu_fast(pv.y + qm.y);
        ov.z = elu_fast(pv.z + qm.z);
        ov.w = elu_fast(pv.w + qm.w);
        *(float4*)(OUT + ((size_t)g * NPG + i) * HID + fo) = ov;
    }
}

// ---------------- sum-pool + output MLP -------------------------------------
__global__ __launch_bounds__(128) void pool_mlp(
    const float* __restrict__ X,
    const float* __restrict__ w1, const float* __restrict__ b1,
    const float* __restrict__ w2, const float* __restrict__ b2,
    const float* __restrict__ w3, const float* __restrict__ b3,
    const float* __restrict__ w4, const float* __restrict__ b4,
    float* __restrict__ out)
{
    __shared__ float pooled[128];
    __shared__ float o1[64];
    __shared__ float o2[32];
    __shared__ float o3[32];
    const int g = blockIdx.x, t = threadIdx.x;
    const float* Xg = X + (size_t)g * NPG * HID;

    float s = 0.0f;
    for (int n = 0; n < NPG; n++) s += Xg[n * HID + t];
    pooled[t] = s;
    __syncthreads();

    if (t < 64) {
        float a = b1[t];
        for (int d = 0; d < 128; d++) a += pooled[d] * w1[d * 64 + t];
        o1[t] = elu_fast(a);
    }
    __syncthreads();
    if (t < 32) {
        float a = b2[t];
        for (int d = 0; d < 64; d++) a += o1[d] * w2[d * 32 + t];
        o2[t] = elu_fast(a);
    }
    __syncthreads();
    if (t < 32) {
        float a = b3[t];
        for (int d = 0; d < 32; d++) a += o2[d] * w3[d * 32 + t];
        o3[t] = elu_fast(a);
    }
    __syncthreads();
    if (t < 6) {
        float a = b4[t];
        for (int d = 0; d < 32; d++) a += o3[d] * w4[d * 6 + t];
        out[g * 6 + t] = a;
    }
}

__global__ void copy_batch(const int* __restrict__ b, float* __restrict__ out)
{
    int i = blockIdx.x * 256 + threadIdx.x;
    if (i < NODES) out[i] = (float)b[i];
}

// ---------------------------------------------------------------------------
extern "C" void kernel_launch(void* const* d_in, const int* in_sizes, int n_in,
                              void* d_out, int out_size)
{
    const float* x_pf    = (const float*)d_in[0];
    const float* enc_w1  = (const float*)d_in[1];
    const float* enc_b1  = (const float*)d_in[2];
    const float* enc_w2  = (const float*)d_in[3];
    const float* enc_b2  = (const float*)d_in[4];
    const float* conv_w[3] = {(const float*)d_in[5], (const float*)d_in[7], (const float*)d_in[9]};
    const float* conv_b[3] = {(const float*)d_in[6], (const float*)d_in[8], (const float*)d_in[10]};
    const float* out_w1  = (const float*)d_in[11];
    const float* out_b1  = (const float*)d_in[12];
    const float* out_w2  = (const float*)d_in[13];
    const float* out_b2  = (const float*)d_in[14];
    const float* out_w3  = (const float*)d_in[15];
    const float* out_b3  = (const float*)d_in[16];
    const float* out_w4  = (const float*)d_in[17];
    const float* out_b4  = (const float*)d_in[18];
    const int*   batch   = (const int*)d_in[19];

    float *featA, *featB, *pq, *wc3;
    cudaGetSymbolAddress((void**)&featA, g_feat_a);
    cudaGetSymbolAddress((void**)&featB, g_feat_b);
    cudaGetSymbolAddress((void**)&pq,    g_pq);
    cudaGetSymbolAddress((void**)&wc3,   g_wc3);

    cudaFuncSetAttribute(mm_kernel, cudaFuncAttributeMaxDynamicSharedMemorySize, MM_SMEM);
    cudaFuncSetAttribute(knn_agg,   cudaFuncAttributeMaxDynamicSharedMemorySize, SMEM_KNN);

    // weight concat for all 3 convs upfront
    for (int c = 0; c < 3; c++)
        build_wcat<<<128, 256>>>(conv_w[c], wc3 + c * HID * 2 * HID);

    // encoder
    mm_kernel<<<dim3(NODES / 128, 1), 256, MM_SMEM>>>(x_pf,  enc_w1, enc_b1, 128, 1, featB, 128, 16);
    mm_kernel<<<dim3(NODES / 128, 1), 256, MM_SMEM>>>(featB, enc_w2, enc_b2, 128, 1, featA, 128, 128);

    // 3 dynamic edge convs
    float* cur = featA;
    float* nxt = featB;
    for (int cidx = 0; cidx < 3; cidx++) {
        mm_kernel<<<dim3(NODES / 128, 2), 256, MM_SMEM>>>(cur, wc3 + cidx * HID * 2 * HID,
                                                          conv_b[cidx], 128, 0, pq, 2 * HID, HID);
        knn_agg<<<2 * NG, 512, SMEM_KNN>>>(cur, pq, nxt);
        float* t = cur; cur = nxt; nxt = t;
    }

    pool_mlp<<<NG, 128>>>(cur, out_w1, out_b1, out_w2, out_b2,
                          out_w3, out_b3, out_w4, out_b4, (float*)d_out);

    copy_batch<<<(NODES + 255) / 256, 256>>>(batch, (float*)d_out + NG * 6);
}

// round 14
// speedup vs baseline: 1.0791x; 1.0791x over previous
#include <cuda_runtime.h>
#include <cstdint>

#define NODES   16384
#define NPG     128
#define NG      128
#define HID     128
#define KNN     24
#define SXT_S   132

typedef unsigned long long u64;

// ---------------- scratch ----------------
__device__ float g_feat_a[NODES * HID];
__device__ float g_feat_b[NODES * HID];
__device__ float g_pq[NODES * 2 * HID];
__device__ float g_wc3[3 * HID * 2 * HID];

__device__ __forceinline__ float elu_fast(float v) {
    return v > 0.0f ? v : (__expf(v) - 1.0f);
}

__device__ __forceinline__ unsigned fkey(float v) {
    unsigned b = __float_as_uint(v);
    return b ^ ((b & 0x80000000u) ? 0xffffffffu : 0x80000000u);
}

// ---- packed fp32x2 helpers (sm_103a FFMA2) ----
__device__ __forceinline__ u64 pack2(float lo, float hi) {
    u64 r; asm("mov.b64 %0,{%1,%2};" : "=l"(r) : "f"(lo), "f"(hi)); return r;
}
__device__ __forceinline__ void unpack2(u64 v, float& lo, float& hi) {
    asm("mov.b64 {%0,%1},%2;" : "=f"(lo), "=f"(hi) : "l"(v));
}
__device__ __forceinline__ void dfma(u64& d, u64 a, u64 b) {
    asm("fma.rn.f32x2 %0,%1,%2,%0;" : "+l"(d) : "l"(a), "l"(b));
}

// ---- cp.async helpers ----
__device__ __forceinline__ void cp16(void* smem, const void* gmem) {
    unsigned s = (unsigned)__cvta_generic_to_shared(smem);
    asm volatile("cp.async.cg.shared.global [%0], [%1], 16;\n" :: "r"(s), "l"(gmem));
}
__device__ __forceinline__ void cp_commit() { asm volatile("cp.async.commit_group;\n"); }
__device__ __forceinline__ void cp_wait0()  { asm volatile("cp.async.wait_group 0;\n"); }

// ---------------- pipelined 128x128-tile fp32 matmul (FFMA2) ---------------
// (R5 code, verified: pq mm 31.4us) — used for the pq matmuls.
__global__ __launch_bounds__(256, 2) void mm_kernel(
    const float* __restrict__ A, const float* __restrict__ B,
    const float* __restrict__ bias, int biasLimit, int doElu,
    float* __restrict__ C, int N, int K)
{
    extern __shared__ float smf[];
    float* As = smf;                   // [2][16*132]
    float* Bs = smf + 2 * 16 * 132;    // [2][16*128]

    const int tid = threadIdx.x;
    const int tx = tid & 15;
    const int ty = tid >> 4;
    const int rowBase = blockIdx.x * 128;
    const int colBase = blockIdx.y * 128;

    u64 acc2[4][8];
#pragma unroll
    for (int r = 0; r < 4; r++)
#pragma unroll
        for (int c = 0; c < 8; c++) acc2[r][c] = 0ull;

    int am[8], ak[8];
#pragma unroll
    for (int t = 0; t < 8; t++) {
        int idx = t * 256 + tid;
        am[t] = idx >> 4; ak[t] = idx & 15;
    }
    int bk[2], bn[2];
#pragma unroll
    for (int t = 0; t < 2; t++) {
        int idx = t * 256 + tid;
        bk[t] = idx >> 5;
        bn[t] = (idx & 31) * 4;
    }

    float aReg[8];
#pragma unroll
    for (int t = 0; t < 8; t++)
        aReg[t] = A[(size_t)(rowBase + am[t]) * K + ak[t]];
#pragma unroll
    for (int t = 0; t < 2; t++)
        cp16(&Bs[bk[t] * 128 + bn[t]], &B[(size_t)bk[t] * N + colBase + bn[t]]);
    cp_commit();
#pragma unroll
    for (int t = 0; t < 8; t++)
        As[ak[t] * 132 + am[t]] = aReg[t];
    cp_wait0();
    __syncthreads();

    int buf = 0;
    for (int kk = 0; kk < K; kk += 16) {
        const int nkk = kk + 16;
        if (nkk < K) {
#pragma unroll
            for (int t = 0; t < 8; t++)
                aReg[t] = A[(size_t)(rowBase + am[t]) * K + nkk + ak[t]];
#pragma unroll
            for (int t = 0; t < 2; t++)
                cp16(&Bs[(buf ^ 1) * 2048 + bk[t] * 128 + bn[t]],
                     &B[(size_t)(nkk + bk[t]) * N + colBase + bn[t]]);
            cp_commit();
        }

        const float* Asb = As + buf * 2112;
        const float* Bsb = Bs + buf * 2048;
#pragma unroll
        for (int k = 0; k < 16; k++) {
            const float* ap = &Asb[k * 132 + ty * 8];
            ulonglong2 t0 = *(const ulonglong2*)(ap);
            ulonglong2 t1 = *(const ulonglong2*)(ap + 4);
            u64 a[4] = {t0.x, t0.y, t1.x, t1.y};
            float4 b0 = *(const float4*)&Bsb[k * 128 + tx * 8];
            float4 b1 = *(const float4*)&Bsb[k * 128 + tx * 8 + 4];
            u64 bd[8];
            bd[0] = pack2(b0.x, b0.x); bd[1] = pack2(b0.y, b0.y);
            bd[2] = pack2(b0.z, b0.z); bd[3] = pack2(b0.w, b0.w);
            bd[4] = pack2(b1.x, b1.x); bd[5] = pack2(b1.y, b1.y);
            bd[6] = pack2(b1.z, b1.z); bd[7] = pack2(b1.w, b1.w);
#pragma unroll
            for (int r = 0; r < 4; r++)
#pragma unroll
                for (int c = 0; c < 8; c++) dfma(acc2[r][c], a[r], bd[c]);
        }

        if (nkk < K) {
#pragma unroll
            for (int t = 0; t < 8; t++)
                As[(buf ^ 1) * 2112 + ak[t] * 132 + am[t]] = aReg[t];
            cp_wait0();
            __syncthreads();
            buf ^= 1;
        }
    }

#pragma unroll
    for (int r = 0; r < 4; r++) {
        int row0 = rowBase + ty * 8 + 2 * r;
        float lo[8], hi[8];
#pragma unroll
        for (int c = 0; c < 8; c++) unpack2(acc2[r][c], lo[c], hi[c]);
#pragma unroll
        for (int c = 0; c < 8; c++) {
            int col = colBase + tx * 8 + c;
            if (col < biasLimit) { float bb = bias[col]; lo[c] += bb; hi[c] += bb; }
            if (doElu) { lo[c] = elu_fast(lo[c]); hi[c] = elu_fast(hi[c]); }
        }
        float* p0 = C + (size_t)row0 * N + colBase + tx * 8;
        float* p1 = p0 + N;
        *(float4*)p0       = make_float4(lo[0], lo[1], lo[2], lo[3]);
        *(float4*)(p0 + 4) = make_float4(lo[4], lo[5], lo[6], lo[7]);
        *(float4*)p1       = make_float4(hi[0], hi[1], hi[2], hi[3]);
        *(float4*)(p1 + 4) = make_float4(hi[4], hi[5], hi[6], hi[7]);
    }
}

#define MM_SMEM ((2*16*132 + 2*16*128) * 4)

// ---------------- fused encoder: 64-row tiles, grid 256 = one wave ---------
// out = elu(elu(x*W1 + b1)*W2 + b2), per CTA 64 rows.
// smem: sW2 [128][128]f, sW1 [16][128]f, sXT u64[16][34], sH1 u64[128][34].
#define ENC_SMEM (65536 + 8192 + 4352 + 34816)

__global__ __launch_bounds__(256, 2) void enc_fused(
    const float* __restrict__ X,
    const float* __restrict__ w1, const float* __restrict__ b1,
    const float* __restrict__ w2, const float* __restrict__ b2,
    float* __restrict__ OUT)
{
    extern __shared__ unsigned char smu[];
    float* sW2 = (float*)smu;                        // 65536 B
    float* sW1 = (float*)(smu + 65536);              // 8192 B
    u64*   sXT = (u64*)(smu + 65536 + 8192);         // [16][34]
    u64*   sH1 = (u64*)(smu + 65536 + 8192 + 4352);  // [128][34]

    const int tid = threadIdx.x;
    const int tx = tid & 15;
    const int ty = tid >> 4;
    const int rowBase = blockIdx.x * 64;

    // async: W2 (4096 chunks) + W1 (512 chunks)
#pragma unroll
    for (int t = 0; t < 16; t++) {
        int idx = t * 256 + tid;
        cp16(sW2 + idx * 4, w2 + idx * 4);
    }
#pragma unroll
    for (int t = 0; t < 2; t++) {
        int idx = t * 256 + tid;
        cp16(sW1 + idx * 4, w1 + idx * 4);
    }
    cp_commit();

    // x tile -> transposed u64 row-pairs: sXT[k][mpair]
#pragma unroll
    for (int t = 0; t < 2; t++) {
        int idx = t * 256 + tid;       // 0..511
        int mp = idx >> 4, k = idx & 15;
        float lo = X[(size_t)(rowBase + 2 * mp) * 16 + k];
        float hi = X[(size_t)(rowBase + 2 * mp + 1) * 16 + k];
        sXT[k * 34 + mp] = pack2(lo, hi);
    }
    cp_wait0();
    __syncthreads();

    // phase A: h1 = elu(x*W1 + b1)  (64x128, K=16) -> sH1 transposed
    {
        u64 acc[2][8];
#pragma unroll
        for (int r = 0; r < 2; r++)
#pragma unroll
            for (int c = 0; c < 8; c++) acc[r][c] = 0ull;

#pragma unroll
        for (int k = 0; k < 16; k++) {
            ulonglong2 a01 = *(const ulonglong2*)&sXT[k * 34 + ty * 2];
            u64 a[2] = {a01.x, a01.y};
            float4 v0 = *(const float4*)&sW1[k * 128 + tx * 8];
            float4 v1 = *(const float4*)&sW1[k * 128 + tx * 8 + 4];
            u64 bd[8];
            bd[0] = pack2(v0.x, v0.x); bd[1] = pack2(v0.y, v0.y);
            bd[2] = pack2(v0.z, v0.z); bd[3] = pack2(v0.w, v0.w);
            bd[4] = pack2(v1.x, v1.x); bd[5] = pack2(v1.y, v1.y);
            bd[6] = pack2(v1.z, v1.z); bd[7] = pack2(v1.w, v1.w);
#pragma unroll
            for (int r = 0; r < 2; r++)
#pragma unroll
                for (int c = 0; c < 8; c++) dfma(acc[r][c], a[r], bd[c]);
        }

#pragma unroll
        for (int r = 0; r < 2; r++)
#pragma unroll
            for (int c = 0; c < 8; c++) {
                float lo, hi;
                unpack2(acc[r][c], lo, hi);
                int col = tx * 8 + c;
                float bb = b1[col];
                lo = elu_fast(lo + bb);
                hi = elu_fast(hi + bb);
                sH1[col * 34 + ty * 2 + r] = pack2(lo, hi);
            }
    }
    __syncthreads();

    // phase B: out = elu(h1*W2 + b2)  (64x128, K=128)
    {
        u64 acc[2][8];
#pragma unroll
        for (int r = 0; r < 2; r++)
#pragma unroll
            for (int c = 0; c < 8; c++) acc[r][c] = 0ull;

#pragma unroll 4
        for (int k = 0; k < 128; k++) {
            ulonglong2 a01 = *(const ulonglong2*)&sH1[k * 34 + ty * 2];
            u64 a[2] = {a01.x, a01.y};
            float4 v0 = *(const float4*)&sW2[k * 128 + tx * 8];
            float4 v1 = *(const float4*)&sW2[k * 128 + tx * 8 + 4];
            u64 bd[8];
            bd[0] = pack2(v0.x, v0.x); bd[1] = pack2(v0.y, v0.y);
            bd[2] = pack2(v0.z, v0.z); bd[3] = pack2(v0.w, v0.w);
            bd[4] = pack2(v1.x, v1.x); bd[5] = pack2(v1.y, v1.y);
            bd[6] = pack2(v1.z, v1.z); bd[7] = pack2(v1.w, v1.w);
#pragma unroll
            for (int r = 0; r < 2; r++)
#pragma unroll
                for (int c = 0; c < 8; c++) dfma(acc[r][c], a[r], bd[c]);
        }

#pragma unroll
        for (int r = 0; r < 2; r++) {
            float lo[8], hi[8];
#pragma unroll
            for (int c = 0; c < 8; c++) unpack2(acc[r][c], lo[c], hi[c]);
#pragma unroll
            for (int c = 0; c < 8; c++) {
                float bb = b2[tx * 8 + c];
                lo[c] = elu_fast(lo[c] + bb);
                hi[c] = elu_fast(hi[c] + bb);
            }
            int row0 = rowBase + ty * 4 + 2 * r;
            float* p0 = OUT + (size_t)row0 * 128 + tx * 8;
            float* p1 = p0 + 128;
            *(float4*)p0       = make_float4(lo[0], lo[1], lo[2], lo[3]);
            *(float4*)(p0 + 4) = make_float4(lo[4], lo[5], lo[6], lo[7]);
            *(float4*)p1       = make_float4(hi[0], hi[1], hi[2], hi[3]);
            *(float4*)(p1 + 4) = make_float4(hi[4], hi[5], hi[6], hi[7]);
        }
    }
}

// ---------------- build [Wa-Wb | Wb] ---------------------------------------
__global__ void build_wcat(const float* __restrict__ w, float* __restrict__ wc)
{
    int idx = blockIdx.x * 256 + threadIdx.x;
    int d = idx >> 8;
    int n = idx & 255;
    float v;
    if (n < 128) v = w[d * 128 + n] - w[(128 + d) * 128 + n];
    else         v = w[(128 + d) * 128 + (n - 128)];
    wc[idx] = v;
}

// ---------------- per-HALF-graph kNN + select + aggregate (R10, verified) --
#define KNN_R0   16896
#define SMEM_KNN ((KNN_R0 + 128) * 4 + 64 * KNN * 4)

__global__ __launch_bounds__(512) void knn_agg(
    const float* __restrict__ X, const float* __restrict__ PQ,
    float* __restrict__ OUT)
{
    extern __shared__ float sm[];
    float* sXT = sm;
    float* sQ  = sm;
    float* sSq = sm + KNN_R0;
    int*   sList = (int*)(sSq + 128);

    const int g   = blockIdx.x >> 1;
    const int h   = blockIdx.x & 1;
    const int tid = threadIdx.x;
    const float* Xg  = X  + (size_t)g * NPG * HID;
    const float* PQg = PQ + (size_t)g * NPG * 2 * HID;

    for (int idx = tid; idx < NPG * HID; idx += 512) {
        int n = idx >> 7, f = idx & 127;
        sXT[f * SXT_S + n] = Xg[idx];
    }
    __syncthreads();

    if (tid < 128) {
        float s = 0.0f;
#pragma unroll 8
        for (int d = 0; d < 128; d++) {
            float v = sXT[d * SXT_S + tid];
            s += v * v;
        }
        sSq[tid] = s;
    }
    __syncthreads();

    const int w = tid >> 5;
    const int l = tid & 31;
    const int i0 = h * 64 + w * 4;
    const int j0 = l * 4;

    u64 acc2[2][4];
#pragma unroll
    for (int r = 0; r < 2; r++)
#pragma unroll
        for (int c = 0; c < 4; c++) acc2[r][c] = 0ull;

#pragma unroll 4
    for (int d = 0; d < 128; d++) {
        const float* rowp = sXT + d * SXT_S;
        ulonglong2 a01 = *(const ulonglong2*)(rowp + i0);
        u64 a[2] = {a01.x, a01.y};
        float4 bj = *(const float4*)(rowp + j0);
        u64 bd[4];
        bd[0] = pack2(bj.x, bj.x); bd[1] = pack2(bj.y, bj.y);
        bd[2] = pack2(bj.z, bj.z); bd[3] = pack2(bj.w, bj.w);
#pragma unroll
        for (int r = 0; r < 2; r++)
#pragma unroll
            for (int c = 0; c < 4; c++) dfma(acc2[r][c], a[r], bd[c]);
    }
    __syncthreads();

#pragma unroll
    for (int t = 0; t < 8; t++) {
        int idx = t * 512 + tid;
        int n = idx >> 5, c4 = (idx & 31) * 4;
        cp16(&sQ[n * 128 + c4], &PQg[n * 256 + 128 + c4]);
    }
    cp_commit();

    {
        float sqj[4];
#pragma unroll
        for (int c = 0; c < 4; c++) sqj[c] = sSq[j0 + c];
#pragma unroll
        for (int r = 0; r < 2; r++) {
            int ia = i0 + 2 * r;
            float sqa = sSq[ia], sqb = sSq[ia + 1];
#pragma unroll
            for (int c = 0; c < 4; c++) {
                float lo, hi;
                unpack2(acc2[r][c], lo, hi);
                unsigned kl = fkey(sqa + sqj[c] - 2.0f * lo);
                unsigned kh = fkey(sqb + sqj[c] - 2.0f * hi);
                acc2[r][c] = ((u64)kh << 32) | (u64)kl;
            }
        }
    }

    const unsigned lmask = (1u << l) - 1u;

#pragma unroll 1
    for (int r = 0; r < 2; r++) {
        unsigned ka[2][4];
#pragma unroll
        for (int c = 0; c < 4; c++) {
            ka[0][c] = (unsigned)acc2[r][c];
            ka[1][c] = (unsigned)(acc2[r][c] >> 32);
        }

        unsigned lo0 = 0, hi0 = 0xffffffffu, lo1 = 0, hi1 = 0xffffffffu;
#pragma unroll 1
        for (int it = 0; it < 32; it++) {
            unsigned m0 = lo0 + ((hi0 - lo0) >> 1);
            unsigned m1 = lo1 + ((hi1 - lo1) >> 1);
            int c0 = (ka[0][0] <= m0) + (ka[0][1] <= m0) + (ka[0][2] <= m0) + (ka[0][3] <= m0);
            int c1 = (ka[1][0] <= m1) + (ka[1][1] <= m1) + (ka[1][2] <= m1) + (ka[1][3] <= m1);
            c0 = __reduce_add_sync(0xffffffffu, c0);
            c1 = __reduce_add_sync(0xffffffffu, c1);
            if (c0 >= KNN) hi0 = m0; else lo0 = m0 + 1;
            if (c1 >= KNN) hi1 = m1; else lo1 = m1 + 1;
        }
        const unsigned KV[2] = {lo0, lo1};

#pragma unroll 1
        for (int rr = 0; rr < 2; rr++) {
            const int iloc = w * 4 + 2 * r + rr;
            const unsigned kv = KV[rr];

            int cl = 0;
#pragma unroll
            for (int c = 0; c < 4; c++) cl += (ka[rr][c] < kv) ? 1 : 0;
            int c0tot = __reduce_add_sync(0xffffffffu, cl);
            int rem = KNN - c0tot;

            bool eq[4], sel[4];
            unsigned bal[4];
#pragma unroll
            for (int c = 0; c < 4; c++) {
                eq[c] = (ka[rr][c] == kv);
                bal[c] = __ballot_sync(0xffffffffu, eq[c]);
            }
            int tiesLower = 0;
#pragma unroll
            for (int c = 0; c < 4; c++) tiesLower += __popc(bal[c] & lmask);
            int lp = 0;
#pragma unroll
            for (int c = 0; c < 4; c++) {
                sel[c] = (ka[rr][c] < kv) || (eq[c] && (tiesLower + lp) < rem);
                lp += eq[c] ? 1 : 0;
            }

            unsigned sbal[4];
#pragma unroll
            for (int c = 0; c < 4; c++) sbal[c] = __ballot_sync(0xffffffffu, sel[c]);
            int selLower = 0;
#pragma unroll
            for (int c = 0; c < 4; c++) selLower += __popc(sbal[c] & lmask);
            int sp = 0;
#pragma unroll
            for (int c = 0; c < 4; c++) {
                if (sel[c]) sList[iloc * KNN + selLower + sp] = j0 + c;
                sp += sel[c] ? 1 : 0;
            }
        }
    }

    cp_wait0();
    __syncthreads();

    const int fo = 4 * l;
#pragma unroll 1
    for (int rr = 0; rr < 4; rr++) {
        const int iloc = w * 4 + rr;
        const int i = h * 64 + iloc;
        float4 pv = *(const float4*)(PQg + (size_t)i * 256 + fo);
        float4 qm = make_float4(-3.0e38f, -3.0e38f, -3.0e38f, -3.0e38f);
#pragma unroll 4
        for (int it = 0; it < KNN; it++) {
            int j = sList[iloc * KNN + it];
            float4 qv = *(const float4*)(sQ + j * 128 + fo);
            qm.x = fmaxf(qm.x, qv.x);
            qm.y = fmaxf(qm.y, qv.y);
            qm.z = fmaxf(qm.z, qv.z);
            qm.w = fmaxf(qm.w, qv.w);
        }
        float4 ov;
        ov.x = elu_fast(pv.x + qm.x);
        ov.y = elu_fast(pv.y + qm.y);
        ov.z = elu_fast(pv.z + qm.z);
        ov.w = elu_fast(pv.w + qm.w);
        *(float4*)(OUT + ((size_t)g * NPG + i) * HID + fo) = ov;
    }
}

// ---------------- sum-pool + output MLP -------------------------------------
__global__ __launch_bounds__(128) void pool_mlp(
    const float* __restrict__ X,
    const float* __restrict__ w1, const float* __restrict__ b1,
    const float* __restrict__ w2, const float* __restrict__ b2,
    const float* __restrict__ w3, const float* __restrict__ b3,
    const float* __restrict__ w4, const float* __restrict__ b4,
    float* __restrict__ out)
{
    __shared__ float pooled[128];
    __shared__ float o1[64];
    __shared__ float o2[32];
    __shared__ float o3[32];
    const int g = blockIdx.x, t = threadIdx.x;
    const float* Xg = X + (size_t)g * NPG * HID;

    float s = 0.0f;
    for (int n = 0; n < NPG; n++) s += Xg[n * HID + t];
    pooled[t] = s;
    __syncthreads();

    if (t < 64) {
        float a = b1[t];
        for (int d = 0; d < 128; d++) a += pooled[d] * w1[d * 64 + t];
        o1[t] = elu_fast(a);
    }
    __syncthreads();
    if (t < 32) {
        float a = b2[t];
        for (int d = 0; d < 64; d++) a += o1[d] * w2[d * 32 + t];
        o2[t] = elu_fast(a);
    }
    __syncthreads();
    if (t < 32) {
        float a = b3[t];
        for (int d = 0; d < 32; d++) a += o2[d] * w3[d * 32 + t];
        o3[t] = elu_fast(a);
    }
    __syncthreads();
    if (t < 6) {
        float a = b4[t];
        for (int d = 0; d < 32; d++) a += o3[d] * w4[d * 6 + t];
        out[g * 6 + t] = a;
    }
}

__global__ void copy_batch(const int* __restrict__ b, float* __restrict__ out)
{
    int i = blockIdx.x * 256 + threadIdx.x;
    if (i < NODES) out[i] = (float)b[i];
}

// ---------------------------------------------------------------------------
extern "C" void kernel_launch(void* const* d_in, const int* in_sizes, int n_in,
                              void* d_out, int out_size)
{
    const float* x_pf    = (const float*)d_in[0];
    const float* enc_w1  = (const float*)d_in[1];
    const float* enc_b1  = (const float*)d_in[2];
    const float* enc_w2  = (const float*)d_in[3];
    const float* enc_b2  = (const float*)d_in[4];
    const float* conv_w[3] = {(const float*)d_in[5], (const float*)d_in[7], (const float*)d_in[9]};
    const float* conv_b[3] = {(const float*)d_in[6], (const float*)d_in[8], (const float*)d_in[10]};
    const float* out_w1  = (const float*)d_in[11];
    const float* out_b1  = (const float*)d_in[12];
    const float* out_w2  = (const float*)d_in[13];
    const float* out_b2  = (const float*)d_in[14];
    const float* out_w3  = (const float*)d_in[15];
    const float* out_b3  = (const float*)d_in[16];
    const float* out_w4  = (const float*)d_in[17];
    const float* out_b4  = (const float*)d_in[18];
    const int*   batch   = (const int*)d_in[19];

    float *featA, *featB, *pq, *wc3;
    cudaGetSymbolAddress((void**)&featA, g_feat_a);
    cudaGetSymbolAddress((void**)&featB, g_feat_b);
    cudaGetSymbolAddress((void**)&pq,    g_pq);
    cudaGetSymbolAddress((void**)&wc3,   g_wc3);

    cudaFuncSetAttribute(mm_kernel, cudaFuncAttributeMaxDynamicSharedMemorySize, MM_SMEM);
    cudaFuncSetAttribute(knn_agg,   cudaFuncAttributeMaxDynamicSharedMemorySize, SMEM_KNN);
    cudaFuncSetAttribute(enc_fused, cudaFuncAttributeMaxDynamicSharedMemorySize, ENC_SMEM);

    // weight concat for all 3 convs upfront
    for (int c = 0; c < 3; c++)
        build_wcat<<<128, 256>>>(conv_w[c], wc3 + c * HID * 2 * HID);

    // fused encoder: one wave of 256 CTAs
    enc_fused<<<256, 256, ENC_SMEM>>>(x_pf, enc_w1, enc_b1, enc_w2, enc_b2, featA);

    // 3 dynamic edge convs
    float* cur = featA;
    float* nxt = featB;
    for (int cidx = 0; cidx < 3; cidx++) {
        mm_kernel<<<dim3(NODES / 128, 2), 256, MM_SMEM>>>(cur, wc3 + cidx * HID * 2 * HID,
                                                          conv_b[cidx], 128, 0, pq, 2 * HID, HID);
        knn_agg<<<2 * NG, 512, SMEM_KNN>>>(cur, pq, nxt);
        float* t = cur; cur = nxt; nxt = t;
    }

    pool_mlp<<<NG, 128>>>(cur, out_w1, out_b1, out_w2, out_b2,
                          out_w3, out_b3, out_w4, out_b4, (float*)d_out);

    copy_batch<<<(NODES + 255) / 256, 256>>>(batch, (float*)d_out + NG * 6);
}